// round 16
// baseline (speedup 1.0000x reference)
#include <cuda_runtime.h>
#include <cuda_bf16.h>
#include <cuda_fp16.h>
#include <cstdint>
#include <math.h>

#define S_LEN 2048
#define BATCH 4
#define HID   1024
#define NH    16
#define DH    64
#define M_TOT (BATCH * S_LEN)      // 8192
#define FILLV (-10000000000000.0f)

#define BETA_C 0.984375f           // 1 - 2^-6
#define INVB   64.0f               // 1/beta
#define LOG2E  1.4426950408889634f
#define M_INIT (-50.0f)
#define M_TH   8.0f

// Scratch (device globals: no allocations allowed)
__device__ __half g_xqh[M_TOT * HID], g_xqu[M_TOT * HID];
__device__ __half g_xkh[M_TOT * HID], g_xku[M_TOT * HID];
__device__ __half g_xvh[M_TOT * HID], g_xvu[M_TOT * HID];
__device__ __half g_wqh[HID * HID], g_wqv[HID * HID];
__device__ __half g_wkh[HID * HID], g_wkv[HID * HID];
__device__ __half g_wvh[HID * HID], g_wvv[HID * HID];
__device__ __half g_woh[HID * HID], g_wov[HID * HID];
__device__ __half g_Q16h[M_TOT * HID], g_Q16u[M_TOT * HID];
__device__ __half g_K16h[M_TOT * HID], g_K16v[M_TOT * HID];
__device__ __half g_V16h[M_TOT * HID], g_V16v[M_TOT * HID];
__device__ __half g_A16h[M_TOT * HID], g_A16u[M_TOT * HID];

// ===========================================================================
// helpers
// ===========================================================================
__device__ __forceinline__ uint32_t smem_u32(const void* p) {
    uint32_t a;
    asm("{ .reg .u64 t; cvta.to.shared.u64 t, %1; cvt.u32.u64 %0, t; }"
        : "=r"(a) : "l"(p));
    return a;
}

__device__ __forceinline__ float fexp2(float x) {
    float r;
    asm("ex2.approx.ftz.f32 %0, %1;" : "=f"(r) : "f"(x));
    return r;
}

#define LDSM_X4(r0, r1, r2, r3, addr)                                         \
    asm volatile("ldmatrix.sync.aligned.m8n8.x4.shared.b16 {%0,%1,%2,%3}, [%4];" \
                 : "=r"(r0), "=r"(r1), "=r"(r2), "=r"(r3) : "r"(addr))

#define LDSM_X4_T(r0, r1, r2, r3, addr)                                       \
    asm volatile("ldmatrix.sync.aligned.m8n8.x4.trans.shared.b16 {%0,%1,%2,%3}, [%4];" \
                 : "=r"(r0), "=r"(r1), "=r"(r2), "=r"(r3) : "r"(addr))

#define MMA16816H(d, a0, a1, a2, a3, b0, b1)                                  \
    asm volatile("mma.sync.aligned.m16n8k16.row.col.f32.f16.f16.f32 "         \
                 "{%0,%1,%2,%3}, {%4,%5,%6,%7}, {%8,%9}, {%0,%1,%2,%3};"      \
                 : "+f"((d)[0]), "+f"((d)[1]), "+f"((d)[2]), "+f"((d)[3])     \
                 : "r"(a0), "r"(a1), "r"(a2), "r"(a3), "r"(b0), "r"(b1))

#define CP_ASYNC16(dst, src)                                                  \
    asm volatile("cp.async.cg.shared.global [%0], [%1], 16;"                  \
                 :: "r"(dst), "l"(src) : "memory")
#define CP_COMMIT() asm volatile("cp.async.commit_group;" ::: "memory")
#define CP_WAIT(n)  asm volatile("cp.async.wait_group %0;" :: "n"(n) : "memory")

#define BAR_G(id) asm volatile("bar.sync %0, %1;" :: "r"(id), "r"(128) : "memory")

// fp16 A-side fold pair: h = rn16(x), u = rn16(x - (1-beta)*h)
__device__ __forceinline__ void split2h(float x, float y, uint32_t& h, uint32_t& u) {
    __half hx = __float2half_rn(x);
    __half hy = __float2half_rn(y);
    h = (uint32_t)__half_as_ushort(hx) | ((uint32_t)__half_as_ushort(hy) << 16);
    __half ux = __float2half_rn(fmaf(-BETA_C, __half2float(hx), x));
    __half uy = __float2half_rn(fmaf(-BETA_C, __half2float(hy), y));
    u = (uint32_t)__half_as_ushort(ux) | ((uint32_t)__half_as_ushort(uy) << 16);
}

// fp16 B-side fold pair: h = rn16(w), v = rn16((w - (1-beta)*h) * 64)
__device__ __forceinline__ void split2hw(float x, float y, uint32_t& h, uint32_t& v) {
    __half hx = __float2half_rn(x);
    __half hy = __float2half_rn(y);
    h = (uint32_t)__half_as_ushort(hx) | ((uint32_t)__half_as_ushort(hy) << 16);
    __half vx = __float2half_rn(fmaf(-BETA_C, __half2float(hx), x) * INVB);
    __half vy = __float2half_rn(fmaf(-BETA_C, __half2float(hy), y) * INVB);
    v = (uint32_t)__half_as_ushort(vx) | ((uint32_t)__half_as_ushort(vy) << 16);
}

// 128-byte-row XOR swizzle
__device__ __forceinline__ uint32_t off128(int row, int u) {
    return (uint32_t)(row * 128 + (((u ^ (row & 7))) << 4));
}

// ===========================================================================
// fused split pass
// ===========================================================================
struct SplitBatch {
    const float* src[7];
    __half*      dh[7];
    __half*      du[7];
    int          n4[7];
};

__global__ void __launch_bounds__(256)
split_all(SplitBatch s)
{
    const int t = blockIdx.y;
    const int i = blockIdx.x * 256 + threadIdx.x;
    if (i < s.n4[t]) {
        float4 v = ((const float4*)s.src[t])[i];
        uint2 h, u;
        if (t < 3) {
            split2h(v.x, v.y, h.x, u.x);
            split2h(v.z, v.w, h.y, u.y);
        } else {
            split2hw(v.x, v.y, h.x, u.x);
            split2hw(v.z, v.w, h.y, u.y);
        }
        ((uint2*)s.dh[t])[i] = h;
        ((uint2*)s.du[t])[i] = u;
    }
}

// ===========================================================================
// GEMM (round-13 verified): fp16 fold, 128x64 CTA, BK=64, 2-stage, 2 CTA/SM.
// ===========================================================================
#define GK 1024
#define NCH2 16
#define GSTAGE3 49152
#define GEMM_SMEM3 (2 * GSTAGE3)

struct GemmBatch {
    const __half* ah[3];
    const __half* au[3];
    const __half* wh[3];
    const __half* wv[3];
    const float*  bias[3];
    __half*       ch[3];
    __half*       cu[3];
    float*        c32[3];
    float         sc[3];
    int           mode[3];
};

__global__ void __launch_bounds__(256, 2)
gemm_h4(GemmBatch gb)
{
    extern __shared__ __align__(128) uint8_t smg[];
    const uint32_t sb = smem_u32(smg);
    const int tid  = threadIdx.x;
    const int lane = tid & 31;
    const int warp = tid >> 5;
    const int wm   = warp >> 1;
    const int wn   = warp & 1;
    const int bm   = blockIdx.y * 128;
    const int bn   = blockIdx.x * 64;
    const int z    = blockIdx.z;
    const int lr   = lane & 7;
    const int ml   = lane >> 3;

    const __half* srcs[4] = {
        gb.ah[z] + (size_t)bm * GK, gb.au[z] + (size_t)bm * GK,
        gb.wh[z] + (size_t)bn * GK, gb.wv[z] + (size_t)bn * GK };

    const int r0 = tid >> 3, g0 = tid & 7;

    int rowA[2], xorA[2];
#pragma unroll
    for (int mt = 0; mt < 2; mt++) {
        int row = wm * 32 + mt * 16 + (ml & 1) * 8 + lr;
        rowA[mt] = row * 128;
        xorA[mt] = row & 7;
    }
    int rowW[2], xorW[2];
#pragma unroll
    for (int p = 0; p < 2; p++) {
        int row = wn * 32 + p * 16 + (ml >> 1) * 8 + lr;
        rowW[p] = row * 128;
        xorW[p] = row & 7;
    }
    const int gA = ml >> 1;
    const int gW = ml & 1;

    float accP[2][4][4], accS[2][4][4];
#pragma unroll
    for (int mt = 0; mt < 2; mt++)
#pragma unroll
        for (int nt = 0; nt < 4; nt++)
#pragma unroll
            for (int r = 0; r < 4; r++) { accP[mt][nt][r] = 0.0f; accS[mt][nt][r] = 0.0f; }

    auto issue = [&](int t) {
        const uint32_t stg = sb + (uint32_t)(t & 1) * GSTAGE3;
        const int kc = t * 64;
#pragma unroll
        for (int m = 0; m < 2; m++) {
            const __half* s = srcs[m] + kc + g0 * 8;
#pragma unroll
            for (int j = 0; j < 4; j++) {
                int row = r0 + j * 32;
                CP_ASYNC16(stg + m * 16384 + off128(row, g0),
                           s + (size_t)row * GK);
            }
        }
#pragma unroll
        for (int m = 0; m < 2; m++) {
            const __half* s = srcs[2 + m] + kc + g0 * 8;
#pragma unroll
            for (int j = 0; j < 2; j++) {
                int row = r0 + j * 32;
                CP_ASYNC16(stg + 32768 + m * 8192 + off128(row, g0),
                           s + (size_t)row * GK);
            }
        }
        CP_COMMIT();
    };

    issue(0);
    issue(1);

    for (int c = 0; c < NCH2; c++) {
        CP_WAIT(1);
        __syncthreads();

        const uint32_t stg = sb + (uint32_t)(c & 1) * GSTAGE3;

#pragma unroll
        for (int ks = 0; ks < 4; ks++) {
            uint32_t ah[2][4], ua[2][4], wh[2][4], vw[2][4];
#pragma unroll
            for (int mt = 0; mt < 2; mt++) {
                uint32_t off = (uint32_t)rowA[mt]
                             + (((uint32_t)((ks * 2 + gA) ^ xorA[mt])) << 4);
                LDSM_X4(ah[mt][0], ah[mt][1], ah[mt][2], ah[mt][3], stg + off);
                LDSM_X4(ua[mt][0], ua[mt][1], ua[mt][2], ua[mt][3], stg + 16384 + off);
            }
#pragma unroll
            for (int p = 0; p < 2; p++) {
                uint32_t off = (uint32_t)rowW[p]
                             + (((uint32_t)((ks * 2 + gW) ^ xorW[p])) << 4);
                LDSM_X4(wh[p][0], wh[p][1], wh[p][2], wh[p][3], stg + 32768 + off);
                LDSM_X4(vw[p][0], vw[p][1], vw[p][2], vw[p][3], stg + 40960 + off);
            }
#pragma unroll
            for (int mt = 0; mt < 2; mt++)
#pragma unroll
                for (int p = 0; p < 2; p++)
#pragma unroll
                    for (int j2 = 0; j2 < 2; j2++)
                        MMA16816H(accP[mt][2 * p + j2],
                                  ah[mt][0], ah[mt][1], ah[mt][2], ah[mt][3],
                                  wh[p][2 * j2], wh[p][2 * j2 + 1]);
#pragma unroll
            for (int mt = 0; mt < 2; mt++)
#pragma unroll
                for (int p = 0; p < 2; p++)
#pragma unroll
                    for (int j2 = 0; j2 < 2; j2++)
                        MMA16816H(accS[mt][2 * p + j2],
                                  ua[mt][0], ua[mt][1], ua[mt][2], ua[mt][3],
                                  vw[p][2 * j2], vw[p][2 * j2 + 1]);
        }

        __syncthreads();
        if (c + 2 < NCH2) issue(c + 2);
        else              CP_COMMIT();
    }

    const float* bias = gb.bias[z];
    const float  sc   = gb.sc[z];
    const int    mode = gb.mode[z];
#pragma unroll
    for (int mt = 0; mt < 2; mt++) {
        int r0g = bm + wm * 32 + mt * 16 + (lane >> 2);
#pragma unroll
        for (int nt = 0; nt < 4; nt++) {
            int cg = bn + wn * 32 + nt * 8 + (lane & 3) * 2;
            float2 bz = *(const float2*)(bias + cg);
            float d0 = fmaf(BETA_C, accP[mt][nt][0], accS[mt][nt][0]);
            float d1 = fmaf(BETA_C, accP[mt][nt][1], accS[mt][nt][1]);
            float d2 = fmaf(BETA_C, accP[mt][nt][2], accS[mt][nt][2]);
            float d3 = fmaf(BETA_C, accP[mt][nt][3], accS[mt][nt][3]);
            float2 v0 = make_float2((d0 + bz.x) * sc, (d1 + bz.y) * sc);
            float2 v1 = make_float2((d2 + bz.x) * sc, (d3 + bz.y) * sc);
            if (mode == 0) {
                *(float2*)(gb.c32[z] + (size_t)r0g * HID + cg)       = v0;
                *(float2*)(gb.c32[z] + (size_t)(r0g + 8) * HID + cg) = v1;
            } else {
                uint32_t h, u;
                if (mode == 1) split2h(v0.x, v0.y, h, u);
                else           split2hw(v0.x, v0.y, h, u);
                *(uint32_t*)(gb.ch[z] + (size_t)r0g * HID + cg) = h;
                *(uint32_t*)(gb.cu[z] + (size_t)r0g * HID + cg) = u;
                if (mode == 1) split2h(v1.x, v1.y, h, u);
                else           split2hw(v1.x, v1.y, h, u);
                *(uint32_t*)(gb.ch[z] + (size_t)(r0g + 8) * HID + cg) = h;
                *(uint32_t*)(gb.cu[z] + (size_t)(r0g + 8) * HID + cg) = u;
            }
        }
    }
}

// ===========================================================================
// Split-KV flash attention, fp16 fold, exp2 domain.
// Round-16: DEFERRED RESCALE — m is a reference max, updated only when a
// warp vote sees rowmax > m + M_TH. Common path: p = ex2(s - m_ref) with
// loop-invariant m_ref; no corr, no O/l scaling. O,l stay in scale
// exp2(-m_ref); normalization/merge math unchanged.
// ===========================================================================
#define XCH_M 148480
#define XCH_L 148736
#define XCH_O 148992
#define FLASH_SMEM 165376

__global__ void __launch_bounds__(256)
flash_sk(const __half* __restrict__ Qhp, const __half* __restrict__ Qup,
         const __half* __restrict__ Khp, const __half* __restrict__ Kvp,
         const __half* __restrict__ Vhp, const __half* __restrict__ Vvp,
         const float* __restrict__ maskg,
         __half* __restrict__ Ahp, __half* __restrict__ Aup)
{
    extern __shared__ __align__(128) uint8_t sbuf[];
    const uint32_t sb = smem_u32(sbuf);

    const int tid  = threadIdx.x;
    const int lane = tid & 31;
    const int w    = tid >> 5;
    const int lr   = lane & 7;
    const int ml   = lane >> 3;
    const int qb   = (int)gridDim.x - 1 - (int)blockIdx.x;
    const int h    = blockIdx.y;
    const int b    = blockIdx.z;
    const int q0   = qb * 64;
    const size_t base = ((size_t)b * S_LEN) * HID + (size_t)h * DH;

#pragma unroll
    for (int j = 0; j < 4; j++) {
        int f = tid + j * 256;
        int term = f >> 9;
        int c = f & 511;
        int row = c >> 3, qq = c & 7;
        CP_ASYNC16(sb + (uint32_t)term * 8192 + off128(row, qq),
                   (term ? Qup : Qhp) + base + (size_t)(q0 + row) * HID + qq * 8);
    }
    CP_COMMIT();
    CP_WAIT(0);
    __syncthreads();

    uint32_t qh[4][4], qu[4][4];
    {
        int row = (w & 3) * 16 + (ml & 1) * 8 + lr;
#pragma unroll
        for (int ks = 0; ks < 4; ks++) {
            uint32_t off = off128(row, ks * 2 + (ml >> 1));
            LDSM_X4(qh[ks][0], qh[ks][1], qh[ks][2], qh[ks][3], sb + off);
            LDSM_X4(qu[ks][0], qu[ks][1], qu[ks][2], qu[ks][3], sb + 8192 + off);
        }
    }

    const int g      = w >> 2;
    const int wg_tid = tid & 127;
    const int barid  = g + 1;

    auto issue_g = [&](int t) {
        if (t <= qb) {
            const int k0t = t * 64;
            const __half* bs[4] = {
                Khp + base + (size_t)k0t * HID,
                Kvp + base + (size_t)k0t * HID,
                Vhp + base + (size_t)k0t * HID,
                Vvp + base + (size_t)k0t * HID };
            const uint32_t stg = sb + 16384u + (uint32_t)g * 65536u
                               + (uint32_t)((t >> 1) & 1) * 32768u;
#pragma unroll
            for (int j = 0; j < 16; j++) {
                int f = wg_tid + j * 128;
                int m = f >> 9, row = (f >> 3) & 63, g0 = f & 7;
                CP_ASYNC16(stg + (uint32_t)m * 8192 + off128(row, g0),
                           bs[m] + (size_t)row * HID + g0 * 8);
            }
            if (wg_tid < 16)
                CP_ASYNC16(sb + 147456u + (uint32_t)(g * 2 + ((t >> 1) & 1)) * 256u
                               + wg_tid * 16,
                           maskg + (size_t)b * S_LEN + k0t + wg_tid * 4);
        }
        CP_COMMIT();
    };

    issue_g(g);
    issue_g(g + 2);

    float oP[8][4], oS[8][4];
#pragma unroll
    for (int ns = 0; ns < 8; ns++)
#pragma unroll
        for (int r = 0; r < 4; r++) { oP[ns][r] = 0.0f; oS[ns][r] = 0.0f; }
    float m0 = M_INIT, m1 = M_INIT, l0 = 0.0f, l1 = 0.0f;

    const int r0g  = q0 + (w & 3) * 16 + (lane >> 2);
    const int cloc = (lane & 3) * 2;

    for (int t = g; t <= qb; t += 2) {
        const int k0 = t * 64;
        CP_WAIT(1);
        BAR_G(barid);

        const uint32_t stg = sb + 16384u + (uint32_t)g * 65536u
                           + (uint32_t)((t >> 1) & 1) * 32768u;
        const uint32_t sKh = stg, sKv = stg + 8192;
        const uint32_t sVh = stg + 16384, sVv = stg + 24576;
        const float* smask = (const float*)(sbuf + 147456
                           + (g * 2 + ((t >> 1) & 1)) * 256);

        float sP[8][4], sS[8][4];
#pragma unroll
        for (int nt = 0; nt < 8; nt++)
#pragma unroll
            for (int r = 0; r < 4; r++) { sP[nt][r] = 0.0f; sS[nt][r] = 0.0f; }

#pragma unroll
        for (int ks = 0; ks < 4; ks++) {
            uint32_t kh[4][4], kv[4][4];
            int rowb = (ml >> 1) * 8 + lr;
            int u    = ks * 2 + (ml & 1);
#pragma unroll
            for (int gg = 0; gg < 4; gg++) {
                int row = gg * 16 + rowb;
                uint32_t off = off128(row, u);
                LDSM_X4(kh[gg][0], kh[gg][1], kh[gg][2], kh[gg][3], sKh + off);
                LDSM_X4(kv[gg][0], kv[gg][1], kv[gg][2], kv[gg][3], sKv + off);
            }
#pragma unroll
            for (int gg = 0; gg < 4; gg++)
#pragma unroll
                for (int j2 = 0; j2 < 2; j2++)
                    MMA16816H(sP[2 * gg + j2], qh[ks][0], qh[ks][1], qh[ks][2], qh[ks][3],
                              kh[gg][2 * j2], kh[gg][2 * j2 + 1]);
#pragma unroll
            for (int gg = 0; gg < 4; gg++)
#pragma unroll
                for (int j2 = 0; j2 < 2; j2++)
                    MMA16816H(sS[2 * gg + j2], qu[ks][0], qu[ks][1], qu[ks][2], qu[ks][3],
                              kv[gg][2 * j2], kv[gg][2 * j2 + 1]);
        }

        float sacc[8][4];
#pragma unroll
        for (int nt = 0; nt < 8; nt++)
#pragma unroll
            for (int r = 0; r < 4; r++)
                sacc[nt][r] = fmaf(BETA_C, sP[nt][r], sS[nt][r]);

        float rm0 = -INFINITY, rm1 = -INFINITY;
        if (t == qb) {
#pragma unroll
            for (int nt = 0; nt < 8; nt++) {
                int c0 = nt * 8 + cloc;
                float mk0 = smask[c0], mk1 = smask[c0 + 1];
                int jg0 = k0 + c0, jg1 = jg0 + 1;
                sacc[nt][0] = (jg0 > r0g     || mk0 == 0.0f) ? FILLV : sacc[nt][0];
                sacc[nt][1] = (jg1 > r0g     || mk1 == 0.0f) ? FILLV : sacc[nt][1];
                sacc[nt][2] = (jg0 > r0g + 8 || mk0 == 0.0f) ? FILLV : sacc[nt][2];
                sacc[nt][3] = (jg1 > r0g + 8 || mk1 == 0.0f) ? FILLV : sacc[nt][3];
                rm0 = fmaxf(rm0, fmaxf(sacc[nt][0], sacc[nt][1]));
                rm1 = fmaxf(rm1, fmaxf(sacc[nt][2], sacc[nt][3]));
            }
        } else {
#pragma unroll
            for (int nt = 0; nt < 8; nt++) {
                int c0 = nt * 8 + cloc;
                float mk0 = smask[c0], mk1 = smask[c0 + 1];
                sacc[nt][0] = (mk0 == 0.0f) ? FILLV : sacc[nt][0];
                sacc[nt][1] = (mk1 == 0.0f) ? FILLV : sacc[nt][1];
                sacc[nt][2] = (mk0 == 0.0f) ? FILLV : sacc[nt][2];
                sacc[nt][3] = (mk1 == 0.0f) ? FILLV : sacc[nt][3];
                rm0 = fmaxf(rm0, fmaxf(sacc[nt][0], sacc[nt][1]));
                rm1 = fmaxf(rm1, fmaxf(sacc[nt][2], sacc[nt][3]));
            }
        }
        rm0 = fmaxf(rm0, __shfl_xor_sync(0xffffffffu, rm0, 1));
        rm0 = fmaxf(rm0, __shfl_xor_sync(0xffffffffu, rm0, 2));
        rm1 = fmaxf(rm1, __shfl_xor_sync(0xffffffffu, rm1, 1));
        rm1 = fmaxf(rm1, __shfl_xor_sync(0xffffffffu, rm1, 2));

        // speculative exp2 against the loop-invariant reference max
#pragma unroll
        for (int nt = 0; nt < 8; nt++) {
            sacc[nt][0] = fexp2(sacc[nt][0] - m0);
            sacc[nt][1] = fexp2(sacc[nt][1] - m0);
            sacc[nt][2] = fexp2(sacc[nt][2] - m1);
            sacc[nt][3] = fexp2(sacc[nt][3] - m1);
        }

        // rare rescale path (warp vote)
        bool need = (rm0 > m0 + M_TH) || (rm1 > m1 + M_TH);
        if (__any_sync(0xffffffffu, need)) {
            float mn0 = fmaxf(m0, rm0), mn1 = fmaxf(m1, rm1);
            float corr0 = fexp2(m0 - mn0), corr1 = fexp2(m1 - mn1);
            m0 = mn0; m1 = mn1;
            l0 *= corr0; l1 *= corr1;
#pragma unroll
            for (int ns = 0; ns < 8; ns++) {
                oP[ns][0] *= corr0; oP[ns][1] *= corr0;
                oP[ns][2] *= corr1; oP[ns][3] *= corr1;
                oS[ns][0] *= corr0; oS[ns][1] *= corr0;
                oS[ns][2] *= corr1; oS[ns][3] *= corr1;
            }
#pragma unroll
            for (int nt = 0; nt < 8; nt++) {
                sacc[nt][0] *= corr0; sacc[nt][1] *= corr0;
                sacc[nt][2] *= corr1; sacc[nt][3] *= corr1;
            }
        }

        float rs0 = 0.0f, rs1 = 0.0f;
#pragma unroll
        for (int nt = 0; nt < 8; nt++) {
            rs0 += sacc[nt][0] + sacc[nt][1];
            rs1 += sacc[nt][2] + sacc[nt][3];
        }
        rs0 += __shfl_xor_sync(0xffffffffu, rs0, 1);
        rs0 += __shfl_xor_sync(0xffffffffu, rs0, 2);
        rs1 += __shfl_xor_sync(0xffffffffu, rs1, 1);
        rs1 += __shfl_xor_sync(0xffffffffu, rs1, 2);
        l0 += rs0;
        l1 += rs1;

#pragma unroll
        for (int ks = 0; ks < 4; ks++) {
            uint32_t ph[4], pu[4];
            split2h(sacc[2 * ks][0],     sacc[2 * ks][1],     ph[0], pu[0]);
            split2h(sacc[2 * ks][2],     sacc[2 * ks][3],     ph[1], pu[1]);
            split2h(sacc[2 * ks + 1][0], sacc[2 * ks + 1][1], ph[2], pu[2]);
            split2h(sacc[2 * ks + 1][2], sacc[2 * ks + 1][3], ph[3], pu[3]);

            int rowv = ks * 16 + (ml & 1) * 8 + lr;
#pragma unroll
            for (int np = 0; np < 4; np++) {
                int u = np * 2 + (ml >> 1);
                uint32_t off = off128(rowv, u);
                uint32_t vh[4], vv[4];
                LDSM_X4_T(vh[0], vh[1], vh[2], vh[3], sVh + off);
                LDSM_X4_T(vv[0], vv[1], vv[2], vv[3], sVv + off);
                MMA16816H(oP[2 * np],     ph[0], ph[1], ph[2], ph[3], vh[0], vh[1]);
                MMA16816H(oP[2 * np + 1], ph[0], ph[1], ph[2], ph[3], vh[2], vh[3]);
                MMA16816H(oS[2 * np],     pu[0], pu[1], pu[2], pu[3], vv[0], vv[1]);
                MMA16816H(oS[2 * np + 1], pu[0], pu[1], pu[2], pu[3], vv[2], vv[3]);
            }
        }

        BAR_G(barid);
        issue_g(t + 4);
    }

    float oacc[8][4];
#pragma unroll
    for (int ns = 0; ns < 8; ns++)
#pragma unroll
        for (int r = 0; r < 4; r++)
            oacc[ns][r] = fmaf(BETA_C, oP[ns][r], oS[ns][r]);

    float* XM = (float*)(sbuf + XCH_M);
    float* XL = (float*)(sbuf + XCH_L);
    float* XO = (float*)(sbuf + XCH_O);
    const int rl = (w & 3) * 16 + (lane >> 2);

    if (g == 1) {
        if ((lane & 3) == 0) {
            XM[rl] = m0; XM[rl + 8] = m1;
            XL[rl] = l0; XL[rl + 8] = l1;
        }
#pragma unroll
        for (int ns = 0; ns < 8; ns++) {
            int col = ns * 8 + cloc;
            *(float2*)&XO[rl * 64 + col]       = make_float2(oacc[ns][0], oacc[ns][1]);
            *(float2*)&XO[(rl + 8) * 64 + col] = make_float2(oacc[ns][2], oacc[ns][3]);
        }
    }
    __syncthreads();
    if (g == 0) {
        float mB0 = XM[rl], mB1 = XM[rl + 8];
        float lB0 = XL[rl], lB1 = XL[rl + 8];
        float mm0 = fmaxf(m0, mB0), mm1 = fmaxf(m1, mB1);
        float a0 = fexp2(m0 - mm0), b0f = fexp2(mB0 - mm0);
        float a1 = fexp2(m1 - mm1), b1f = fexp2(mB1 - mm1);
        float li0 = 1.0f / (l0 * a0 + lB0 * b0f);
        float li1 = 1.0f / (l1 * a1 + lB1 * b1f);
#pragma unroll
        for (int ns = 0; ns < 8; ns++) {
            int col = ns * 8 + cloc;
            float2 ob0 = *(const float2*)&XO[rl * 64 + col];
            float2 ob1 = *(const float2*)&XO[(rl + 8) * 64 + col];
            float o00 = (oacc[ns][0] * a0 + ob0.x * b0f) * li0;
            float o01 = (oacc[ns][1] * a0 + ob0.y * b0f) * li0;
            float o10 = (oacc[ns][2] * a1 + ob1.x * b1f) * li1;
            float o11 = (oacc[ns][3] * a1 + ob1.y * b1f) * li1;
            uint32_t hh, uu;
            split2h(o00, o01, hh, uu);
            *(uint32_t*)(Ahp + base + (size_t)(q0 + rl) * HID + col) = hh;
            *(uint32_t*)(Aup + base + (size_t)(q0 + rl) * HID + col) = uu;
            split2h(o10, o11, hh, uu);
            *(uint32_t*)(Ahp + base + (size_t)(q0 + rl + 8) * HID + col) = hh;
            *(uint32_t*)(Aup + base + (size_t)(q0 + rl + 8) * HID + col) = uu;
        }
    }
}

// ---------------------------------------------------------------------------
extern "C" void kernel_launch(void* const* d_in, const int* in_sizes, int n_in,
                              void* d_out, int out_size)
{
    const float* q    = (const float*)d_in[0];
    const float* k    = (const float*)d_in[1];
    const float* v    = (const float*)d_in[2];
    const float* mask = (const float*)d_in[3];
    const float* Wq   = (const float*)d_in[4];
    const float* bq   = (const float*)d_in[5];
    const float* Wk   = (const float*)d_in[6];
    const float* bk   = (const float*)d_in[7];
    const float* Wv   = (const float*)d_in[8];
    const float* bv   = (const float*)d_in[9];
    const float* Wo   = (const float*)d_in[10];
    const float* bo   = (const float*)d_in[11];
    float* out = (float*)d_out;

    __half *xqh, *xqu, *xkh, *xku, *xvh, *xvu;
    __half *wqh, *wqv, *wkh, *wkv, *wvh, *wvv, *woh, *wov;
    __half *Q16h, *Q16u, *K16h, *K16v, *V16h, *V16v, *A16h, *A16u;
    cudaGetSymbolAddress((void**)&xqh, g_xqh); cudaGetSymbolAddress((void**)&xqu, g_xqu);
    cudaGetSymbolAddress((void**)&xkh, g_xkh); cudaGetSymbolAddress((void**)&xku, g_xku);
    cudaGetSymbolAddress((void**)&xvh, g_xvh); cudaGetSymbolAddress((void**)&xvu, g_xvu);
    cudaGetSymbolAddress((void**)&wqh, g_wqh); cudaGetSymbolAddress((void**)&wqv, g_wqv);
    cudaGetSymbolAddress((void**)&wkh, g_wkh); cudaGetSymbolAddress((void**)&wkv, g_wkv);
    cudaGetSymbolAddress((void**)&wvh, g_wvh); cudaGetSymbolAddress((void**)&wvv, g_wvv);
    cudaGetSymbolAddress((void**)&woh, g_woh); cudaGetSymbolAddress((void**)&wov, g_wov);
    cudaGetSymbolAddress((void**)&Q16h, g_Q16h); cudaGetSymbolAddress((void**)&Q16u, g_Q16u);
    cudaGetSymbolAddress((void**)&K16h, g_K16h); cudaGetSymbolAddress((void**)&K16v, g_K16v);
    cudaGetSymbolAddress((void**)&V16h, g_V16h); cudaGetSymbolAddress((void**)&V16v, g_V16v);
    cudaGetSymbolAddress((void**)&A16h, g_A16h); cudaGetSymbolAddress((void**)&A16u, g_A16u);

    cudaFuncSetAttribute(flash_sk, cudaFuncAttributeMaxDynamicSharedMemorySize,
                         FLASH_SMEM);
    cudaFuncSetAttribute(gemm_h4, cudaFuncAttributeMaxDynamicSharedMemorySize,
                         GEMM_SMEM3);

    const int n4x = M_TOT * HID / 4;
    const int n4w = HID * HID / 4;

    SplitBatch sbt;
    sbt.src[0] = q;  sbt.dh[0] = xqh; sbt.du[0] = xqu; sbt.n4[0] = n4x;
    sbt.src[1] = k;  sbt.dh[1] = xkh; sbt.du[1] = xku; sbt.n4[1] = n4x;
    sbt.src[2] = v;  sbt.dh[2] = xvh; sbt.du[2] = xvu; sbt.n4[2] = n4x;
    sbt.src[3] = Wq; sbt.dh[3] = wqh; sbt.du[3] = wqv; sbt.n4[3] = n4w;
    sbt.src[4] = Wk; sbt.dh[4] = wkh; sbt.du[4] = wkv; sbt.n4[4] = n4w;
    sbt.src[5] = Wv; sbt.dh[5] = wvh; sbt.du[5] = wvv; sbt.n4[5] = n4w;
    sbt.src[6] = Wo; sbt.dh[6] = woh; sbt.du[6] = wov; sbt.n4[6] = n4w;
    split_all<<<dim3(n4x / 256, 7), 256>>>(sbt);

    GemmBatch gqkv = {};
    gqkv.ah[0] = xqh; gqkv.au[0] = xqu; gqkv.wh[0] = wqh; gqkv.wv[0] = wqv;
    gqkv.bias[0] = bq; gqkv.ch[0] = Q16h; gqkv.cu[0] = Q16u;
    gqkv.sc[0] = 0.125f * LOG2E; gqkv.mode[0] = 1;   // Q: scaled to exp2 domain
    gqkv.ah[1] = xkh; gqkv.au[1] = xku; gqkv.wh[1] = wkh; gqkv.wv[1] = wkv;
    gqkv.bias[1] = bk; gqkv.ch[1] = K16h; gqkv.cu[1] = K16v;
    gqkv.sc[1] = 1.0f; gqkv.mode[1] = 2;             // K: B-side pair
    gqkv.ah[2] = xvh; gqkv.au[2] = xvu; gqkv.wh[2] = wvh; gqkv.wv[2] = wvv;
    gqkv.bias[2] = bv; gqkv.ch[2] = V16h; gqkv.cu[2] = V16v;
    gqkv.sc[2] = 1.0f; gqkv.mode[2] = 2;             // V: B-side pair
    gemm_h4<<<dim3(HID / 64, M_TOT / 128, 3), 256, GEMM_SMEM3>>>(gqkv);

    flash_sk<<<dim3(S_LEN / 64, NH, BATCH), 256, FLASH_SMEM>>>(
        Q16h, Q16u, K16h, K16v, V16h, V16v, mask, A16h, A16u);

    GemmBatch gout = {};
    gout.ah[0] = A16h; gout.au[0] = A16u; gout.wh[0] = woh; gout.wv[0] = wov;
    gout.bias[0] = bo; gout.c32[0] = out; gout.sc[0] = 1.0f; gout.mode[0] = 0;
    gemm_h4<<<dim3(HID / 64, M_TOT / 128, 1), 256, GEMM_SMEM3>>>(gout);
}

// round 17
// speedup vs baseline: 1.0950x; 1.0950x over previous
#include <cuda_runtime.h>
#include <cuda_bf16.h>
#include <cuda_fp16.h>
#include <cstdint>
#include <math.h>

#define S_LEN 2048
#define BATCH 4
#define HID   1024
#define NH    16
#define DH    64
#define M_TOT (BATCH * S_LEN)      // 8192
#define FILLV (-10000000000000.0f)

#define BETA_C 0.984375f           // 1 - 2^-6
#define INVB   64.0f               // 1/beta
#define LOG2E  1.4426950408889634f

// Scratch (device globals: no allocations allowed)
__device__ __half g_xqh[M_TOT * HID], g_xqu[M_TOT * HID];
__device__ __half g_xkh[M_TOT * HID], g_xku[M_TOT * HID];
__device__ __half g_xvh[M_TOT * HID], g_xvu[M_TOT * HID];
__device__ __half g_wqh[HID * HID], g_wqv[HID * HID];
__device__ __half g_wkh[HID * HID], g_wkv[HID * HID];
__device__ __half g_wvh[HID * HID], g_wvv[HID * HID];
__device__ __half g_woh[HID * HID], g_wov[HID * HID];
__device__ __half g_Q16h[M_TOT * HID], g_Q16u[M_TOT * HID];
__device__ __half g_K16h[M_TOT * HID], g_K16v[M_TOT * HID];
__device__ __half g_V16 [M_TOT * HID];
__device__ __half g_A16h[M_TOT * HID], g_A16u[M_TOT * HID];

// ===========================================================================
// helpers
// ===========================================================================
__device__ __forceinline__ uint32_t smem_u32(const void* p) {
    uint32_t a;
    asm("{ .reg .u64 t; cvta.to.shared.u64 t, %1; cvt.u32.u64 %0, t; }"
        : "=r"(a) : "l"(p));
    return a;
}

__device__ __forceinline__ float fexp2(float x) {
    float r;
    asm("ex2.approx.ftz.f32 %0, %1;" : "=f"(r) : "f"(x));
    return r;
}

// pack two fp32 -> fp16x2 (element0 = x in low half)
__device__ __forceinline__ uint32_t packh2(float x, float y) {
    uint32_t r;
    asm("cvt.rn.f16x2.f32 %0, %1, %2;" : "=r"(r) : "f"(y), "f"(x));
    return r;
}

#define LDSM_X4(r0, r1, r2, r3, addr)                                         \
    asm volatile("ldmatrix.sync.aligned.m8n8.x4.shared.b16 {%0,%1,%2,%3}, [%4];" \
                 : "=r"(r0), "=r"(r1), "=r"(r2), "=r"(r3) : "r"(addr))

#define LDSM_X4_T(r0, r1, r2, r3, addr)                                       \
    asm volatile("ldmatrix.sync.aligned.m8n8.x4.trans.shared.b16 {%0,%1,%2,%3}, [%4];" \
                 : "=r"(r0), "=r"(r1), "=r"(r2), "=r"(r3) : "r"(addr))

#define MMA16816H(d, a0, a1, a2, a3, b0, b1)                                  \
    asm volatile("mma.sync.aligned.m16n8k16.row.col.f32.f16.f16.f32 "         \
                 "{%0,%1,%2,%3}, {%4,%5,%6,%7}, {%8,%9}, {%0,%1,%2,%3};"      \
                 : "+f"((d)[0]), "+f"((d)[1]), "+f"((d)[2]), "+f"((d)[3])     \
                 : "r"(a0), "r"(a1), "r"(a2), "r"(a3), "r"(b0), "r"(b1))

#define CP_ASYNC16(dst, src)                                                  \
    asm volatile("cp.async.cg.shared.global [%0], [%1], 16;"                  \
                 :: "r"(dst), "l"(src) : "memory")
#define CP_COMMIT() asm volatile("cp.async.commit_group;" ::: "memory")
#define CP_WAIT(n)  asm volatile("cp.async.wait_group %0;" :: "n"(n) : "memory")

#define BAR_G(id) asm volatile("bar.sync %0, %1;" :: "r"(id), "r"(128) : "memory")

// fp16 A-side fold pair: h = rn16(x), u = rn16(x - (1-beta)*h)
__device__ __forceinline__ void split2h(float x, float y, uint32_t& h, uint32_t& u) {
    __half hx = __float2half_rn(x);
    __half hy = __float2half_rn(y);
    h = (uint32_t)__half_as_ushort(hx) | ((uint32_t)__half_as_ushort(hy) << 16);
    __half ux = __float2half_rn(fmaf(-BETA_C, __half2float(hx), x));
    __half uy = __float2half_rn(fmaf(-BETA_C, __half2float(hy), y));
    u = (uint32_t)__half_as_ushort(ux) | ((uint32_t)__half_as_ushort(uy) << 16);
}

// fp16 B-side fold pair: h = rn16(w), v = rn16((w - (1-beta)*h) * 64)
__device__ __forceinline__ void split2hw(float x, float y, uint32_t& h, uint32_t& v) {
    __half hx = __float2half_rn(x);
    __half hy = __float2half_rn(y);
    h = (uint32_t)__half_as_ushort(hx) | ((uint32_t)__half_as_ushort(hy) << 16);
    __half vx = __float2half_rn(fmaf(-BETA_C, __half2float(hx), x) * INVB);
    __half vy = __float2half_rn(fmaf(-BETA_C, __half2float(hy), y) * INVB);
    v = (uint32_t)__half_as_ushort(vx) | ((uint32_t)__half_as_ushort(vy) << 16);
}

// 128-byte-row XOR swizzle
__device__ __forceinline__ uint32_t off128(int row, int u) {
    return (uint32_t)(row * 128 + (((u ^ (row & 7))) << 4));
}

// ===========================================================================
// fused split pass
// ===========================================================================
struct SplitBatch {
    const float* src[7];
    __half*      dh[7];
    __half*      du[7];
    int          n4[7];
};

__global__ void __launch_bounds__(256)
split_all(SplitBatch s)
{
    const int t = blockIdx.y;
    const int i = blockIdx.x * 256 + threadIdx.x;
    if (i < s.n4[t]) {
        float4 v = ((const float4*)s.src[t])[i];
        uint2 h, u;
        if (t < 3) {
            split2h(v.x, v.y, h.x, u.x);
            split2h(v.z, v.w, h.y, u.y);
        } else {
            split2hw(v.x, v.y, h.x, u.x);
            split2hw(v.z, v.w, h.y, u.y);
        }
        ((uint2*)s.dh[t])[i] = h;
        ((uint2*)s.du[t])[i] = u;
    }
}

// ===========================================================================
// GEMM (round-13 verified): fp16 fold, 128x64 CTA, BK=64, 2-stage, 2 CTA/SM.
// Epilogue modes: 0 = fp32, 1 = A-side fold pair, 2 = B-side fold pair,
//                 3 = single rn fp16.
// ===========================================================================
#define GK 1024
#define NCH2 16
#define GSTAGE3 49152
#define GEMM_SMEM3 (2 * GSTAGE3)

struct GemmBatch {
    const __half* ah[3];
    const __half* au[3];
    const __half* wh[3];
    const __half* wv[3];
    const float*  bias[3];
    __half*       ch[3];
    __half*       cu[3];
    float*        c32[3];
    float         sc[3];
    int           mode[3];
};

__global__ void __launch_bounds__(256, 2)
gemm_h4(GemmBatch gb)
{
    extern __shared__ __align__(128) uint8_t smg[];
    const uint32_t sb = smem_u32(smg);
    const int tid  = threadIdx.x;
    const int lane = tid & 31;
    const int warp = tid >> 5;
    const int wm   = warp >> 1;
    const int wn   = warp & 1;
    const int bm   = blockIdx.y * 128;
    const int bn   = blockIdx.x * 64;
    const int z    = blockIdx.z;
    const int lr   = lane & 7;
    const int ml   = lane >> 3;

    const __half* srcs[4] = {
        gb.ah[z] + (size_t)bm * GK, gb.au[z] + (size_t)bm * GK,
        gb.wh[z] + (size_t)bn * GK, gb.wv[z] + (size_t)bn * GK };

    const int r0 = tid >> 3, g0 = tid & 7;

    int rowA[2], xorA[2];
#pragma unroll
    for (int mt = 0; mt < 2; mt++) {
        int row = wm * 32 + mt * 16 + (ml & 1) * 8 + lr;
        rowA[mt] = row * 128;
        xorA[mt] = row & 7;
    }
    int rowW[2], xorW[2];
#pragma unroll
    for (int p = 0; p < 2; p++) {
        int row = wn * 32 + p * 16 + (ml >> 1) * 8 + lr;
        rowW[p] = row * 128;
        xorW[p] = row & 7;
    }
    const int gA = ml >> 1;
    const int gW = ml & 1;

    float accP[2][4][4], accS[2][4][4];
#pragma unroll
    for (int mt = 0; mt < 2; mt++)
#pragma unroll
        for (int nt = 0; nt < 4; nt++)
#pragma unroll
            for (int r = 0; r < 4; r++) { accP[mt][nt][r] = 0.0f; accS[mt][nt][r] = 0.0f; }

    auto issue = [&](int t) {
        const uint32_t stg = sb + (uint32_t)(t & 1) * GSTAGE3;
        const int kc = t * 64;
#pragma unroll
        for (int m = 0; m < 2; m++) {
            const __half* s = srcs[m] + kc + g0 * 8;
#pragma unroll
            for (int j = 0; j < 4; j++) {
                int row = r0 + j * 32;
                CP_ASYNC16(stg + m * 16384 + off128(row, g0),
                           s + (size_t)row * GK);
            }
        }
#pragma unroll
        for (int m = 0; m < 2; m++) {
            const __half* s = srcs[2 + m] + kc + g0 * 8;
#pragma unroll
            for (int j = 0; j < 2; j++) {
                int row = r0 + j * 32;
                CP_ASYNC16(stg + 32768 + m * 8192 + off128(row, g0),
                           s + (size_t)row * GK);
            }
        }
        CP_COMMIT();
    };

    issue(0);
    issue(1);

    for (int c = 0; c < NCH2; c++) {
        CP_WAIT(1);
        __syncthreads();

        const uint32_t stg = sb + (uint32_t)(c & 1) * GSTAGE3;

#pragma unroll
        for (int ks = 0; ks < 4; ks++) {
            uint32_t ah[2][4], ua[2][4], wh[2][4], vw[2][4];
#pragma unroll
            for (int mt = 0; mt < 2; mt++) {
                uint32_t off = (uint32_t)rowA[mt]
                             + (((uint32_t)((ks * 2 + gA) ^ xorA[mt])) << 4);
                LDSM_X4(ah[mt][0], ah[mt][1], ah[mt][2], ah[mt][3], stg + off);
                LDSM_X4(ua[mt][0], ua[mt][1], ua[mt][2], ua[mt][3], stg + 16384 + off);
            }
#pragma unroll
            for (int p = 0; p < 2; p++) {
                uint32_t off = (uint32_t)rowW[p]
                             + (((uint32_t)((ks * 2 + gW) ^ xorW[p])) << 4);
                LDSM_X4(wh[p][0], wh[p][1], wh[p][2], wh[p][3], stg + 32768 + off);
                LDSM_X4(vw[p][0], vw[p][1], vw[p][2], vw[p][3], stg + 40960 + off);
            }
#pragma unroll
            for (int mt = 0; mt < 2; mt++)
#pragma unroll
                for (int p = 0; p < 2; p++)
#pragma unroll
                    for (int j2 = 0; j2 < 2; j2++)
                        MMA16816H(accP[mt][2 * p + j2],
                                  ah[mt][0], ah[mt][1], ah[mt][2], ah[mt][3],
                                  wh[p][2 * j2], wh[p][2 * j2 + 1]);
#pragma unroll
            for (int mt = 0; mt < 2; mt++)
#pragma unroll
                for (int p = 0; p < 2; p++)
#pragma unroll
                    for (int j2 = 0; j2 < 2; j2++)
                        MMA16816H(accS[mt][2 * p + j2],
                                  ua[mt][0], ua[mt][1], ua[mt][2], ua[mt][3],
                                  vw[p][2 * j2], vw[p][2 * j2 + 1]);
        }

        __syncthreads();
        if (c + 2 < NCH2) issue(c + 2);
        else              CP_COMMIT();
    }

    const float* bias = gb.bias[z];
    const float  sc   = gb.sc[z];
    const int    mode = gb.mode[z];
#pragma unroll
    for (int mt = 0; mt < 2; mt++) {
        int r0g = bm + wm * 32 + mt * 16 + (lane >> 2);
#pragma unroll
        for (int nt = 0; nt < 4; nt++) {
            int cg = bn + wn * 32 + nt * 8 + (lane & 3) * 2;
            float2 bz = *(const float2*)(bias + cg);
            float d0 = fmaf(BETA_C, accP[mt][nt][0], accS[mt][nt][0]);
            float d1 = fmaf(BETA_C, accP[mt][nt][1], accS[mt][nt][1]);
            float d2 = fmaf(BETA_C, accP[mt][nt][2], accS[mt][nt][2]);
            float d3 = fmaf(BETA_C, accP[mt][nt][3], accS[mt][nt][3]);
            float2 v0 = make_float2((d0 + bz.x) * sc, (d1 + bz.y) * sc);
            float2 v1 = make_float2((d2 + bz.x) * sc, (d3 + bz.y) * sc);
            if (mode == 0) {
                *(float2*)(gb.c32[z] + (size_t)r0g * HID + cg)       = v0;
                *(float2*)(gb.c32[z] + (size_t)(r0g + 8) * HID + cg) = v1;
            } else if (mode == 3) {
                *(uint32_t*)(gb.ch[z] + (size_t)r0g * HID + cg)       = packh2(v0.x, v0.y);
                *(uint32_t*)(gb.ch[z] + (size_t)(r0g + 8) * HID + cg) = packh2(v1.x, v1.y);
            } else {
                uint32_t h, u;
                if (mode == 1) split2h(v0.x, v0.y, h, u);
                else           split2hw(v0.x, v0.y, h, u);
                *(uint32_t*)(gb.ch[z] + (size_t)r0g * HID + cg) = h;
                *(uint32_t*)(gb.cu[z] + (size_t)r0g * HID + cg) = u;
                if (mode == 1) split2h(v1.x, v1.y, h, u);
                else           split2hw(v1.x, v1.y, h, u);
                *(uint32_t*)(gb.ch[z] + (size_t)(r0g + 8) * HID + cg) = h;
                *(uint32_t*)(gb.cu[z] + (size_t)(r0g + 8) * HID + cg) = u;
            }
        }
    }
}

// ===========================================================================
// Split-KV flash attention, exp2 domain. Round-17: PV fold DROPPED —
// P single rn fp16 (one cvt per pair), V single rn fp16 (one tile per stage).
// S keeps the fold (logit precision). smem: Q@0(16K);
// group g stages @16384 + g*49152 + s*24576 (Kh 8K, Kv 8K, V 8K);
// masks @114688; XCH m@115712 l@115968 O@116224.
// ===========================================================================
#define XCH_M 115712
#define XCH_L 115968
#define XCH_O 116224
#define FLASH_SMEM 132608

__global__ void __launch_bounds__(256)
flash_sk(const __half* __restrict__ Qhp, const __half* __restrict__ Qup,
         const __half* __restrict__ Khp, const __half* __restrict__ Kvp,
         const __half* __restrict__ Vp,
         const float* __restrict__ maskg,
         __half* __restrict__ Ahp, __half* __restrict__ Aup)
{
    extern __shared__ __align__(128) uint8_t sbuf[];
    const uint32_t sb = smem_u32(sbuf);

    const int tid  = threadIdx.x;
    const int lane = tid & 31;
    const int w    = tid >> 5;
    const int lr   = lane & 7;
    const int ml   = lane >> 3;
    const int qb   = (int)gridDim.x - 1 - (int)blockIdx.x;
    const int h    = blockIdx.y;
    const int b    = blockIdx.z;
    const int q0   = qb * 64;
    const size_t base = ((size_t)b * S_LEN) * HID + (size_t)h * DH;

#pragma unroll
    for (int j = 0; j < 4; j++) {
        int f = tid + j * 256;
        int term = f >> 9;
        int c = f & 511;
        int row = c >> 3, qq = c & 7;
        CP_ASYNC16(sb + (uint32_t)term * 8192 + off128(row, qq),
                   (term ? Qup : Qhp) + base + (size_t)(q0 + row) * HID + qq * 8);
    }
    CP_COMMIT();
    CP_WAIT(0);
    __syncthreads();

    uint32_t qh[4][4], qu[4][4];
    {
        int row = (w & 3) * 16 + (ml & 1) * 8 + lr;
#pragma unroll
        for (int ks = 0; ks < 4; ks++) {
            uint32_t off = off128(row, ks * 2 + (ml >> 1));
            LDSM_X4(qh[ks][0], qh[ks][1], qh[ks][2], qh[ks][3], sb + off);
            LDSM_X4(qu[ks][0], qu[ks][1], qu[ks][2], qu[ks][3], sb + 8192 + off);
        }
    }

    const int g      = w >> 2;
    const int wg_tid = tid & 127;
    const int barid  = g + 1;

    auto issue_g = [&](int t) {
        if (t <= qb) {
            const int k0t = t * 64;
            const __half* bs[3] = {
                Khp + base + (size_t)k0t * HID,
                Kvp + base + (size_t)k0t * HID,
                Vp  + base + (size_t)k0t * HID };
            const uint32_t stg = sb + 16384u + (uint32_t)g * 49152u
                               + (uint32_t)((t >> 1) & 1) * 24576u;
#pragma unroll
            for (int j = 0; j < 12; j++) {
                int f = wg_tid + j * 128;
                int m = f >> 9, row = (f >> 3) & 63, g0 = f & 7;
                CP_ASYNC16(stg + (uint32_t)m * 8192 + off128(row, g0),
                           bs[m] + (size_t)row * HID + g0 * 8);
            }
            if (wg_tid < 16)
                CP_ASYNC16(sb + 114688u + (uint32_t)(g * 2 + ((t >> 1) & 1)) * 256u
                               + wg_tid * 16,
                           maskg + (size_t)b * S_LEN + k0t + wg_tid * 4);
        }
        CP_COMMIT();
    };

    issue_g(g);
    issue_g(g + 2);

    float oacc[8][4];
#pragma unroll
    for (int ns = 0; ns < 8; ns++)
#pragma unroll
        for (int r = 0; r < 4; r++) oacc[ns][r] = 0.0f;
    float m0 = -INFINITY, m1 = -INFINITY, l0 = 0.0f, l1 = 0.0f;

    const int r0g  = q0 + (w & 3) * 16 + (lane >> 2);
    const int cloc = (lane & 3) * 2;

    for (int t = g; t <= qb; t += 2) {
        const int k0 = t * 64;
        CP_WAIT(1);
        BAR_G(barid);

        const uint32_t stg = sb + 16384u + (uint32_t)g * 49152u
                           + (uint32_t)((t >> 1) & 1) * 24576u;
        const uint32_t sKh = stg, sKv = stg + 8192;
        const uint32_t sV  = stg + 16384;
        const float* smask = (const float*)(sbuf + 114688
                           + (g * 2 + ((t >> 1) & 1)) * 256);

        float sP[8][4], sS[8][4];
#pragma unroll
        for (int nt = 0; nt < 8; nt++)
#pragma unroll
            for (int r = 0; r < 4; r++) { sP[nt][r] = 0.0f; sS[nt][r] = 0.0f; }

#pragma unroll
        for (int ks = 0; ks < 4; ks++) {
            uint32_t kh[4][4], kv[4][4];
            int rowb = (ml >> 1) * 8 + lr;
            int u    = ks * 2 + (ml & 1);
#pragma unroll
            for (int gg = 0; gg < 4; gg++) {
                int row = gg * 16 + rowb;
                uint32_t off = off128(row, u);
                LDSM_X4(kh[gg][0], kh[gg][1], kh[gg][2], kh[gg][3], sKh + off);
                LDSM_X4(kv[gg][0], kv[gg][1], kv[gg][2], kv[gg][3], sKv + off);
            }
#pragma unroll
            for (int gg = 0; gg < 4; gg++)
#pragma unroll
                for (int j2 = 0; j2 < 2; j2++)
                    MMA16816H(sP[2 * gg + j2], qh[ks][0], qh[ks][1], qh[ks][2], qh[ks][3],
                              kh[gg][2 * j2], kh[gg][2 * j2 + 1]);
#pragma unroll
            for (int gg = 0; gg < 4; gg++)
#pragma unroll
                for (int j2 = 0; j2 < 2; j2++)
                    MMA16816H(sS[2 * gg + j2], qu[ks][0], qu[ks][1], qu[ks][2], qu[ks][3],
                              kv[gg][2 * j2], kv[gg][2 * j2 + 1]);
        }

        float sacc[8][4];
#pragma unroll
        for (int nt = 0; nt < 8; nt++)
#pragma unroll
            for (int r = 0; r < 4; r++)
                sacc[nt][r] = fmaf(BETA_C, sP[nt][r], sS[nt][r]);

        float rm0 = -INFINITY, rm1 = -INFINITY;
        if (t == qb) {
#pragma unroll
            for (int nt = 0; nt < 8; nt++) {
                int c0 = nt * 8 + cloc;
                float mk0 = smask[c0], mk1 = smask[c0 + 1];
                int jg0 = k0 + c0, jg1 = jg0 + 1;
                sacc[nt][0] = (jg0 > r0g     || mk0 == 0.0f) ? FILLV : sacc[nt][0];
                sacc[nt][1] = (jg1 > r0g     || mk1 == 0.0f) ? FILLV : sacc[nt][1];
                sacc[nt][2] = (jg0 > r0g + 8 || mk0 == 0.0f) ? FILLV : sacc[nt][2];
                sacc[nt][3] = (jg1 > r0g + 8 || mk1 == 0.0f) ? FILLV : sacc[nt][3];
                rm0 = fmaxf(rm0, fmaxf(sacc[nt][0], sacc[nt][1]));
                rm1 = fmaxf(rm1, fmaxf(sacc[nt][2], sacc[nt][3]));
            }
        } else {
#pragma unroll
            for (int nt = 0; nt < 8; nt++) {
                int c0 = nt * 8 + cloc;
                float mk0 = smask[c0], mk1 = smask[c0 + 1];
                sacc[nt][0] = (mk0 == 0.0f) ? FILLV : sacc[nt][0];
                sacc[nt][1] = (mk1 == 0.0f) ? FILLV : sacc[nt][1];
                sacc[nt][2] = (mk0 == 0.0f) ? FILLV : sacc[nt][2];
                sacc[nt][3] = (mk1 == 0.0f) ? FILLV : sacc[nt][3];
                rm0 = fmaxf(rm0, fmaxf(sacc[nt][0], sacc[nt][1]));
                rm1 = fmaxf(rm1, fmaxf(sacc[nt][2], sacc[nt][3]));
            }
        }
        rm0 = fmaxf(rm0, __shfl_xor_sync(0xffffffffu, rm0, 1));
        rm0 = fmaxf(rm0, __shfl_xor_sync(0xffffffffu, rm0, 2));
        rm1 = fmaxf(rm1, __shfl_xor_sync(0xffffffffu, rm1, 1));
        rm1 = fmaxf(rm1, __shfl_xor_sync(0xffffffffu, rm1, 2));

        float mn0 = fmaxf(m0, rm0), mn1 = fmaxf(m1, rm1);
        float corr0 = fexp2(m0 - mn0), corr1 = fexp2(m1 - mn1);
        m0 = mn0; m1 = mn1;

        float rs0 = 0.0f, rs1 = 0.0f;
#pragma unroll
        for (int nt = 0; nt < 8; nt++) {
            sacc[nt][0] = fexp2(sacc[nt][0] - mn0);
            sacc[nt][1] = fexp2(sacc[nt][1] - mn0);
            sacc[nt][2] = fexp2(sacc[nt][2] - mn1);
            sacc[nt][3] = fexp2(sacc[nt][3] - mn1);
            rs0 += sacc[nt][0] + sacc[nt][1];
            rs1 += sacc[nt][2] + sacc[nt][3];
        }
        rs0 += __shfl_xor_sync(0xffffffffu, rs0, 1);
        rs0 += __shfl_xor_sync(0xffffffffu, rs0, 2);
        rs1 += __shfl_xor_sync(0xffffffffu, rs1, 1);
        rs1 += __shfl_xor_sync(0xffffffffu, rs1, 2);
        l0 = l0 * corr0 + rs0;
        l1 = l1 * corr1 + rs1;
#pragma unroll
        for (int ns = 0; ns < 8; ns++) {
            oacc[ns][0] *= corr0; oacc[ns][1] *= corr0;
            oacc[ns][2] *= corr1; oacc[ns][3] *= corr1;
        }

        // ---- O += P V (single rn fp16 P and V: 1 MMA per n-tile step) ----
#pragma unroll
        for (int ks = 0; ks < 4; ks++) {
            uint32_t ph[4];
            ph[0] = packh2(sacc[2 * ks][0],     sacc[2 * ks][1]);
            ph[1] = packh2(sacc[2 * ks][2],     sacc[2 * ks][3]);
            ph[2] = packh2(sacc[2 * ks + 1][0], sacc[2 * ks + 1][1]);
            ph[3] = packh2(sacc[2 * ks + 1][2], sacc[2 * ks + 1][3]);

            int rowv = ks * 16 + (ml & 1) * 8 + lr;
#pragma unroll
            for (int np = 0; np < 4; np++) {
                int u = np * 2 + (ml >> 1);
                uint32_t off = off128(rowv, u);
                uint32_t vh[4];
                LDSM_X4_T(vh[0], vh[1], vh[2], vh[3], sV + off);
                MMA16816H(oacc[2 * np],     ph[0], ph[1], ph[2], ph[3], vh[0], vh[1]);
                MMA16816H(oacc[2 * np + 1], ph[0], ph[1], ph[2], ph[3], vh[2], vh[3]);
            }
        }

        BAR_G(barid);
        issue_g(t + 4);
    }

    float* XM = (float*)(sbuf + XCH_M);
    float* XL = (float*)(sbuf + XCH_L);
    float* XO = (float*)(sbuf + XCH_O);
    const int rl = (w & 3) * 16 + (lane >> 2);

    if (g == 1) {
        if ((lane & 3) == 0) {
            XM[rl] = m0; XM[rl + 8] = m1;
            XL[rl] = l0; XL[rl + 8] = l1;
        }
#pragma unroll
        for (int ns = 0; ns < 8; ns++) {
            int col = ns * 8 + cloc;
            *(float2*)&XO[rl * 64 + col]       = make_float2(oacc[ns][0], oacc[ns][1]);
            *(float2*)&XO[(rl + 8) * 64 + col] = make_float2(oacc[ns][2], oacc[ns][3]);
        }
    }
    __syncthreads();
    if (g == 0) {
        float mB0 = XM[rl], mB1 = XM[rl + 8];
        float lB0 = XL[rl], lB1 = XL[rl + 8];
        float mm0 = fmaxf(m0, mB0), mm1 = fmaxf(m1, mB1);
        float a0 = fexp2(m0 - mm0), b0f = fexp2(mB0 - mm0);
        float a1 = fexp2(m1 - mm1), b1f = fexp2(mB1 - mm1);
        float li0 = 1.0f / (l0 * a0 + lB0 * b0f);
        float li1 = 1.0f / (l1 * a1 + lB1 * b1f);
#pragma unroll
        for (int ns = 0; ns < 8; ns++) {
            int col = ns * 8 + cloc;
            float2 ob0 = *(const float2*)&XO[rl * 64 + col];
            float2 ob1 = *(const float2*)&XO[(rl + 8) * 64 + col];
            float o00 = (oacc[ns][0] * a0 + ob0.x * b0f) * li0;
            float o01 = (oacc[ns][1] * a0 + ob0.y * b0f) * li0;
            float o10 = (oacc[ns][2] * a1 + ob1.x * b1f) * li1;
            float o11 = (oacc[ns][3] * a1 + ob1.y * b1f) * li1;
            uint32_t hh, uu;
            split2h(o00, o01, hh, uu);
            *(uint32_t*)(Ahp + base + (size_t)(q0 + rl) * HID + col) = hh;
            *(uint32_t*)(Aup + base + (size_t)(q0 + rl) * HID + col) = uu;
            split2h(o10, o11, hh, uu);
            *(uint32_t*)(Ahp + base + (size_t)(q0 + rl + 8) * HID + col) = hh;
            *(uint32_t*)(Aup + base + (size_t)(q0 + rl + 8) * HID + col) = uu;
        }
    }
}

// ---------------------------------------------------------------------------
extern "C" void kernel_launch(void* const* d_in, const int* in_sizes, int n_in,
                              void* d_out, int out_size)
{
    const float* q    = (const float*)d_in[0];
    const float* k    = (const float*)d_in[1];
    const float* v    = (const float*)d_in[2];
    const float* mask = (const float*)d_in[3];
    const float* Wq   = (const float*)d_in[4];
    const float* bq   = (const float*)d_in[5];
    const float* Wk   = (const float*)d_in[6];
    const float* bk   = (const float*)d_in[7];
    const float* Wv   = (const float*)d_in[8];
    const float* bv   = (const float*)d_in[9];
    const float* Wo   = (const float*)d_in[10];
    const float* bo   = (const float*)d_in[11];
    float* out = (float*)d_out;

    __half *xqh, *xqu, *xkh, *xku, *xvh, *xvu;
    __half *wqh, *wqv, *wkh, *wkv, *wvh, *wvv, *woh, *wov;
    __half *Q16h, *Q16u, *K16h, *K16v, *V16, *A16h, *A16u;
    cudaGetSymbolAddress((void**)&xqh, g_xqh); cudaGetSymbolAddress((void**)&xqu, g_xqu);
    cudaGetSymbolAddress((void**)&xkh, g_xkh); cudaGetSymbolAddress((void**)&xku, g_xku);
    cudaGetSymbolAddress((void**)&xvh, g_xvh); cudaGetSymbolAddress((void**)&xvu, g_xvu);
    cudaGetSymbolAddress((void**)&wqh, g_wqh); cudaGetSymbolAddress((void**)&wqv, g_wqv);
    cudaGetSymbolAddress((void**)&wkh, g_wkh); cudaGetSymbolAddress((void**)&wkv, g_wkv);
    cudaGetSymbolAddress((void**)&wvh, g_wvh); cudaGetSymbolAddress((void**)&wvv, g_wvv);
    cudaGetSymbolAddress((void**)&woh, g_woh); cudaGetSymbolAddress((void**)&wov, g_wov);
    cudaGetSymbolAddress((void**)&Q16h, g_Q16h); cudaGetSymbolAddress((void**)&Q16u, g_Q16u);
    cudaGetSymbolAddress((void**)&K16h, g_K16h); cudaGetSymbolAddress((void**)&K16v, g_K16v);
    cudaGetSymbolAddress((void**)&V16,  g_V16);
    cudaGetSymbolAddress((void**)&A16h, g_A16h); cudaGetSymbolAddress((void**)&A16u, g_A16u);

    cudaFuncSetAttribute(flash_sk, cudaFuncAttributeMaxDynamicSharedMemorySize,
                         FLASH_SMEM);
    cudaFuncSetAttribute(gemm_h4, cudaFuncAttributeMaxDynamicSharedMemorySize,
                         GEMM_SMEM3);

    const int n4x = M_TOT * HID / 4;
    const int n4w = HID * HID / 4;

    SplitBatch sbt;
    sbt.src[0] = q;  sbt.dh[0] = xqh; sbt.du[0] = xqu; sbt.n4[0] = n4x;
    sbt.src[1] = k;  sbt.dh[1] = xkh; sbt.du[1] = xku; sbt.n4[1] = n4x;
    sbt.src[2] = v;  sbt.dh[2] = xvh; sbt.du[2] = xvu; sbt.n4[2] = n4x;
    sbt.src[3] = Wq; sbt.dh[3] = wqh; sbt.du[3] = wqv; sbt.n4[3] = n4w;
    sbt.src[4] = Wk; sbt.dh[4] = wkh; sbt.du[4] = wkv; sbt.n4[4] = n4w;
    sbt.src[5] = Wv; sbt.dh[5] = wvh; sbt.du[5] = wvv; sbt.n4[5] = n4w;
    sbt.src[6] = Wo; sbt.dh[6] = woh; sbt.du[6] = wov; sbt.n4[6] = n4w;
    split_all<<<dim3(n4x / 256, 7), 256>>>(sbt);

    GemmBatch gqkv = {};
    gqkv.ah[0] = xqh; gqkv.au[0] = xqu; gqkv.wh[0] = wqh; gqkv.wv[0] = wqv;
    gqkv.bias[0] = bq; gqkv.ch[0] = Q16h; gqkv.cu[0] = Q16u;
    gqkv.sc[0] = 0.125f * LOG2E; gqkv.mode[0] = 1;   // Q: A-side fold, exp2 domain
    gqkv.ah[1] = xkh; gqkv.au[1] = xku; gqkv.wh[1] = wkh; gqkv.wv[1] = wkv;
    gqkv.bias[1] = bk; gqkv.ch[1] = K16h; gqkv.cu[1] = K16v;
    gqkv.sc[1] = 1.0f; gqkv.mode[1] = 2;             // K: B-side fold
    gqkv.ah[2] = xvh; gqkv.au[2] = xvu; gqkv.wh[2] = wvh; gqkv.wv[2] = wvv;
    gqkv.bias[2] = bv; gqkv.ch[2] = V16; gqkv.cu[2] = nullptr;
    gqkv.sc[2] = 1.0f; gqkv.mode[2] = 3;             // V: single rn fp16
    gemm_h4<<<dim3(HID / 64, M_TOT / 128, 3), 256, GEMM_SMEM3>>>(gqkv);

    flash_sk<<<dim3(S_LEN / 64, NH, BATCH), 256, FLASH_SMEM>>>(
        Q16h, Q16u, K16h, K16v, V16, mask, A16h, A16u);

    GemmBatch gout = {};
    gout.ah[0] = A16h; gout.au[0] = A16u; gout.wh[0] = woh; gout.wv[0] = wov;
    gout.bias[0] = bo; gout.c32[0] = out; gout.sc[0] = 1.0f; gout.mode[0] = 0;
    gemm_h4<<<dim3(HID / 64, M_TOT / 128, 1), 256, GEMM_SMEM3>>>(gout);
}